// round 15
// baseline (speedup 1.0000x reference)
#include <cuda_runtime.h>
#include <cuda_fp16.h>
#include <cstdint>

#define B_   2
#define N_   2048
#define D_   1024
#define H_   16
#define DH_  64
#define LVLS 11
#define XYR  4096            // padded rows per batch (4095 real + 1 zero)
#define K1   1024

// ---------------- scratch ----------------
__device__ __align__(16) __half g_xy1[(long)B_ * XYR * K1];
__device__ __align__(16) __half g_w1 [4][(long)D_ * K1];
__device__ __align__(16) __half g_a1 [(long)B_ * N_  * K1];
__device__ __align__(16) float  g_Qf [(long)B_ * N_  * D_];
__device__ __align__(16) __half g_Kh [(long)B_ * XYR * D_];
__device__ __align__(16) __half g_Vh [(long)B_ * XYR * D_];

// streams/events created once at load time, BEFORE harness mem checkpoints
struct HxStreams {
    cudaStream_t s1;
    cudaEvent_t eFork, eJoin;
    HxStreams() {
        int lo = 0, hi = 0;
        cudaDeviceGetStreamPriorityRange(&lo, &hi);
        cudaStreamCreateWithPriority(&s1, cudaStreamNonBlocking, lo);
        cudaEventCreateWithFlags(&eFork, cudaEventDisableTiming);
        cudaEventCreateWithFlags(&eJoin, cudaEventDisableTiming);
    }
};
static HxStreams g_hx;

__device__ __forceinline__ uint4 pack8(float4 a, float4 b) {
    __half2 h0 = __floats2half2_rn(a.x, a.y);
    __half2 h1 = __floats2half2_rn(a.z, a.w);
    __half2 h2 = __floats2half2_rn(b.x, b.y);
    __half2 h3 = __floats2half2_rn(b.z, b.w);
    uint4 u;
    u.x = *reinterpret_cast<uint32_t*>(&h0);
    u.y = *reinterpret_cast<uint32_t*>(&h1);
    u.z = *reinterpret_cast<uint32_t*>(&h2);
    u.w = *reinterpret_cast<uint32_t*>(&h3);
    return u;
}

// ---------------- fused prep: 4 weights + xy, one launch, 16B stores ----------------
__global__ void build_all_kernel(const float* __restrict__ q, const float* __restrict__ y,
                                 const float* __restrict__ W0, const float* __restrict__ W1,
                                 const float* __restrict__ W2, const float* __restrict__ W3) {
    const int slot = blockIdx.y;
    if (slot < 4) {
        const float* W;
        switch (slot) {
            case 0: W = W0; break;
            case 1: W = W1; break;
            case 2: W = W2; break;
            default: W = W3; break;
        }
        __half* out = g_w1[slot];
        const long total = (long)D_ * (D_ / 8);
        for (long i = (long)blockIdx.x * blockDim.x + threadIdx.x; i < total;
             i += (long)gridDim.x * blockDim.x) {
            int r = (int)(i >> 7);
            int c = ((int)i & 127) * 8;
            float4 v0 = *(const float4*)&W[(long)r * D_ + c];
            float4 v1 = *(const float4*)&W[(long)r * D_ + c + 4];
            *(uint4*)&out[(long)r * K1 + c] = pack8(v0, v1);
        }
    } else {
        const long quarter = (long)B_ * XYR * (D_ / 8) / 4;
        const long lo = (slot - 4) * quarter;
        const long hi = lo + quarter;
        for (long i = lo + (long)blockIdx.x * blockDim.x + threadIdx.x; i < hi;
             i += (long)gridDim.x * blockDim.x) {
            int r   = (int)(i >> 7);
            int c   = ((int)i & 127) * 8;
            int b   = r >> 12;
            int rr  = r & 4095;
            float4 v0 = make_float4(0.f, 0.f, 0.f, 0.f);
            float4 v1 = v0;
            if (rr < N_) {
                const float* src = &q[((long)(b * N_ + rr)) * D_ + c];
                v0 = *(const float4*)src;
                v1 = *(const float4*)(src + 4);
            } else if (rr < 4095) {
                const float* src = &y[((long)(b * (N_ - 1) + rr - N_)) * D_ + c];
                v0 = *(const float4*)src;
                v1 = *(const float4*)(src + 4);
            }
            *(uint4*)&g_xy1[(long)r * K1 + c] = pack8(v0, v1);
        }
    }
}

// ================ shared GEMM constants ================
#define KST  72
#define NCH (K1 / 64)                       // 16 chunks

// ---------------- QKV GEMM (frozen R10-R14 mainloop), 128x128 tiles ----------------
// One batch, 640 CTAs: [0,256) K, [256,512) V, [512,640) Q.
#define SA_OFF(s) ((s) * (128 * KST))
#define SB_OFF(s) (3 * 128 * KST + (s) * (128 * KST))
#define SM_HALVES (6 * 128 * KST)           // 110592 B per CTA

__global__ __launch_bounds__(256, 2)
void hgemm_qkv(const __half* __restrict__ Axy,
               const __half* __restrict__ wq, const __half* __restrict__ wk,
               const __half* __restrict__ wv,
               float* __restrict__ Qf, __half* __restrict__ Kh, __half* __restrict__ Vh) {
    extern __shared__ __half sm[];

    const __half* Bw;
    float* Cf = nullptr;
    __half* Ch = nullptr;
    bool halfOut = false;
    long row0, col0;
    {
        const int id = blockIdx.x;
        int bx, by;
        if (id < 256) {
            bx = id & 7; by = id >> 3;
            Bw = wk; Ch = Kh; halfOut = true;
        } else if (id < 512) {
            const int r = id - 256;
            bx = r & 7; by = r >> 3;
            Bw = wv; Ch = Vh; halfOut = true;
        } else {
            const int r = id - 512;
            bx = r & 7; by = r >> 3;
            Bw = wq; Cf = Qf;
        }
        row0 = (long)by * 128;
        col0 = (long)bx * 128;
    }

    const int tid  = threadIdx.x;
    const int lane = tid & 31;
    const int warp = tid >> 5;
    const int wm0  = (warp & 1) * 64;
    const int wn0  = (warp >> 1) * 32;

    float acc[4][4][4];
#pragma unroll
    for (int mt = 0; mt < 4; mt++)
#pragma unroll
        for (int nt = 0; nt < 4; nt++)
#pragma unroll
            for (int i = 0; i < 4; i++) acc[mt][nt][i] = 0.f;

    const int aoff = (wm0 + (lane & 15)) * KST + (lane >> 4) * 8;
    const int boff = (wn0 + (lane >> 4) * 8 + (lane & 7)) * KST + ((lane >> 3) & 1) * 8;

    const __half* Abase = Axy + row0 * K1;
    const __half* Bbase = Bw + col0 * K1;

    auto ld_tile = [&](int s, int c) {
        const long k0 = (long)c * 64;
#pragma unroll
        for (int t = 0; t < 4; t++) {
            const int i = tid + t * 256;
            const long r = i >> 3;
            const long cc = (i & 7) * 8;
            uint32_t dst = (uint32_t)__cvta_generic_to_shared(
                &sm[SA_OFF(s) + (int)r * KST + (int)cc]);
            const __half* src = Abase + r * K1 + k0 + cc;
            asm volatile("cp.async.cg.shared.global [%0], [%1], 16;" :: "r"(dst), "l"(src));
        }
#pragma unroll
        for (int t = 0; t < 4; t++) {
            const int i = tid + t * 256;
            const long r = i >> 3;
            const long cc = (i & 7) * 8;
            uint32_t dst = (uint32_t)__cvta_generic_to_shared(
                &sm[SB_OFF(s) + (int)r * KST + (int)cc]);
            const __half* src = Bbase + r * K1 + k0 + cc;
            asm volatile("cp.async.cg.shared.global [%0], [%1], 16;" :: "r"(dst), "l"(src));
        }
    };

    ld_tile(0, 0); asm volatile("cp.async.commit_group;" ::: "memory");
    ld_tile(1, 1); asm volatile("cp.async.commit_group;" ::: "memory");

    for (int c = 0; c < NCH; c++) {
        asm volatile("cp.async.wait_group 1;" ::: "memory");
        __syncthreads();
        if (c + 2 < NCH) ld_tile((c + 2) % 3, c + 2);
        asm volatile("cp.async.commit_group;" ::: "memory");

        const int buf = c % 3;
#pragma unroll
        for (int ks = 0; ks < 4; ks++) {
            uint32_t fa[4][4];
#pragma unroll
            for (int mt = 0; mt < 4; mt++) {
                uint32_t ad = (uint32_t)__cvta_generic_to_shared(
                    &sm[SA_OFF(buf) + aoff + mt * 16 * KST + ks * 16]);
                asm volatile("ldmatrix.sync.aligned.m8n8.x4.shared.b16 {%0,%1,%2,%3}, [%4];\n"
                             : "=r"(fa[mt][0]), "=r"(fa[mt][1]),
                               "=r"(fa[mt][2]), "=r"(fa[mt][3])
                             : "r"(ad));
            }
            uint32_t fb[4][2];
#pragma unroll
            for (int np = 0; np < 2; np++) {
                uint32_t bd = (uint32_t)__cvta_generic_to_shared(
                    &sm[SB_OFF(buf) + boff + np * 16 * KST + ks * 16]);
                uint32_t r0, r1, r2, r3;
                asm volatile("ldmatrix.sync.aligned.m8n8.x4.shared.b16 {%0,%1,%2,%3}, [%4];\n"
                             : "=r"(r0), "=r"(r1), "=r"(r2), "=r"(r3) : "r"(bd));
                fb[np * 2][0] = r0; fb[np * 2][1] = r1;
                fb[np * 2 + 1][0] = r2; fb[np * 2 + 1][1] = r3;
            }
#pragma unroll
            for (int mt = 0; mt < 4; mt++)
#pragma unroll
                for (int nt = 0; nt < 4; nt++) {
                    asm volatile(
                        "mma.sync.aligned.m16n8k16.row.col.f32.f16.f16.f32 "
                        "{%0,%1,%2,%3},{%4,%5,%6,%7},{%8,%9},{%0,%1,%2,%3};\n"
                        : "+f"(acc[mt][nt][0]), "+f"(acc[mt][nt][1]),
                          "+f"(acc[mt][nt][2]), "+f"(acc[mt][nt][3])
                        : "r"(fa[mt][0]), "r"(fa[mt][1]),
                          "r"(fa[mt][2]), "r"(fa[mt][3]),
                          "r"(fb[nt][0]), "r"(fb[nt][1]));
                }
        }
    }

#pragma unroll
    for (int mt = 0; mt < 4; mt++)
#pragma unroll
        for (int nt = 0; nt < 4; nt++) {
            long r = row0 + wm0 + mt * 16 + (lane >> 2);
            long cc = col0 + wn0 + nt * 8 + (lane & 3) * 2;
            if (halfOut) {
                *(__half2*)&Ch[r * D_ + cc] =
                    __floats2half2_rn(acc[mt][nt][0], acc[mt][nt][1]);
                *(__half2*)&Ch[(r + 8) * D_ + cc] =
                    __floats2half2_rn(acc[mt][nt][2], acc[mt][nt][3]);
            } else {
                *(float2*)&Cf[r * D_ + cc] =
                    make_float2(acc[mt][nt][0], acc[mt][nt][1]);
                *(float2*)&Cf[(r + 8) * D_ + cc] =
                    make_float2(acc[mt][nt][2], acc[mt][nt][3]);
            }
        }
}

// ---------------- O GEMM: 64x128 tiles, 256 CTAs per batch ----------------
// 8 warps as 2(M)x4(N), warptile 32x32, BK=64, 3 stages, ~90 regs, 2 CTAs/SM.
#define OA_OFF(s) ((s) * (64 * KST))
#define OB_OFF(s) (3 * 64 * KST + (s) * (128 * KST))
#define SMO_HALVES (3 * 64 * KST + 3 * 128 * KST)   // 41472 halves = 82944 B

__global__ __launch_bounds__(256, 2)
void hgemm_o(const __half* __restrict__ Aatt, const __half* __restrict__ wo,
             float* __restrict__ Out, const float* __restrict__ bias) {
    extern __shared__ __half sm[];

    const int id = blockIdx.x;
    const int bx = id & 7, by = id >> 3;        // 32 row blocks x 8 col blocks
    const long row0 = (long)by * 64;
    const long col0 = (long)bx * 128;

    const int tid  = threadIdx.x;
    const int lane = tid & 31;
    const int warp = tid >> 5;
    const int wm0  = (warp & 1) * 32;           // 2 warps along M (64)
    const int wn0  = (warp >> 1) * 32;          // 4 warps along N (128)

    float acc[2][4][4];
#pragma unroll
    for (int mt = 0; mt < 2; mt++)
#pragma unroll
        for (int nt = 0; nt < 4; nt++)
#pragma unroll
            for (int i = 0; i < 4; i++) acc[mt][nt][i] = 0.f;

    const int aoff = (wm0 + (lane & 15)) * KST + (lane >> 4) * 8;
    const int boff = (wn0 + (lane >> 4) * 8 + (lane & 7)) * KST + ((lane >> 3) & 1) * 8;

    const __half* Abase = Aatt + row0 * K1;
    const __half* Bbase = wo + col0 * K1;

    auto ld_tile = [&](int s, int c) {
        const long k0 = (long)c * 64;
#pragma unroll
        for (int t = 0; t < 2; t++) {          // A: 64 rows x 128B
            const int i = tid + t * 256;
            const long r = i >> 3;
            const long cc = (i & 7) * 8;
            uint32_t dst = (uint32_t)__cvta_generic_to_shared(
                &sm[OA_OFF(s) + (int)r * KST + (int)cc]);
            const __half* src = Abase + r * K1 + k0 + cc;
            asm volatile("cp.async.cg.shared.global [%0], [%1], 16;" :: "r"(dst), "l"(src));
        }
#pragma unroll
        for (int t = 0; t < 4; t++) {          // B: 128 rows x 128B
            const int i = tid + t * 256;
            const long r = i >> 3;
            const long cc = (i & 7) * 8;
            uint32_t dst = (uint32_t)__cvta_generic_to_shared(
                &sm[OB_OFF(s) + (int)r * KST + (int)cc]);
            const __half* src = Bbase + r * K1 + k0 + cc;
            asm volatile("cp.async.cg.shared.global [%0], [%1], 16;" :: "r"(dst), "l"(src));
        }
    };

    ld_tile(0, 0); asm volatile("cp.async.commit_group;" ::: "memory");
    ld_tile(1, 1); asm volatile("cp.async.commit_group;" ::: "memory");

    for (int c = 0; c < NCH; c++) {
        asm volatile("cp.async.wait_group 1;" ::: "memory");
        __syncthreads();
        if (c + 2 < NCH) ld_tile((c + 2) % 3, c + 2);
        asm volatile("cp.async.commit_group;" ::: "memory");

        const int buf = c % 3;
#pragma unroll
        for (int ks = 0; ks < 4; ks++) {
            uint32_t fa[2][4];
#pragma unroll
            for (int mt = 0; mt < 2; mt++) {
                uint32_t ad = (uint32_t)__cvta_generic_to_shared(
                    &sm[OA_OFF(buf) + aoff + mt * 16 * KST + ks * 16]);
                asm volatile("ldmatrix.sync.aligned.m8n8.x4.shared.b16 {%0,%1,%2,%3}, [%4];\n"
                             : "=r"(fa[mt][0]), "=r"(fa[mt][1]),
                               "=r"(fa[mt][2]), "=r"(fa[mt][3])
                             : "r"(ad));
            }
            uint32_t fb[4][2];
#pragma unroll
            for (int np = 0; np < 2; np++) {
                uint32_t bd = (uint32_t)__cvta_generic_to_shared(
                    &sm[OB_OFF(buf) + boff + np * 16 * KST + ks * 16]);
                uint32_t r0, r1, r2, r3;
                asm volatile("ldmatrix.sync.aligned.m8n8.x4.shared.b16 {%0,%1,%2,%3}, [%4];\n"
                             : "=r"(r0), "=r"(r1), "=r"(r2), "=r"(r3) : "r"(bd));
                fb[np * 2][0] = r0; fb[np * 2][1] = r1;
                fb[np * 2 + 1][0] = r2; fb[np * 2 + 1][1] = r3;
            }
#pragma unroll
            for (int mt = 0; mt < 2; mt++)
#pragma unroll
                for (int nt = 0; nt < 4; nt++) {
                    asm volatile(
                        "mma.sync.aligned.m16n8k16.row.col.f32.f16.f16.f32 "
                        "{%0,%1,%2,%3},{%4,%5,%6,%7},{%8,%9},{%0,%1,%2,%3};\n"
                        : "+f"(acc[mt][nt][0]), "+f"(acc[mt][nt][1]),
                          "+f"(acc[mt][nt][2]), "+f"(acc[mt][nt][3])
                        : "r"(fa[mt][0]), "r"(fa[mt][1]),
                          "r"(fa[mt][2]), "r"(fa[mt][3]),
                          "r"(fb[nt][0]), "r"(fb[nt][1]));
                }
        }
    }

#pragma unroll
    for (int mt = 0; mt < 2; mt++)
#pragma unroll
        for (int nt = 0; nt < 4; nt++) {
            long r = row0 + wm0 + mt * 16 + (lane >> 2);
            long cc = col0 + wn0 + nt * 8 + (lane & 3) * 2;
            float2 v0 = make_float2(acc[mt][nt][0], acc[mt][nt][1]);
            float2 v1 = make_float2(acc[mt][nt][2], acc[mt][nt][3]);
            float2 bb = *(const float2*)&bias[cc];
            v0.x += bb.x; v0.y += bb.y; v1.x += bb.x; v1.y += bb.y;
            *(float2*)&Out[r * D_ + cc]       = v0;
            *(float2*)&Out[(r + 8) * D_ + cc] = v1;
        }
}

// ---------------- hierarchical sparse attention (per-batch, fp16 K/V) ----------------
__global__ __launch_bounds__(512)
void attn_kernel(const float* __restrict__ Q, const __half* __restrict__ Kh,
                 const __half* __restrict__ Vh, __half* __restrict__ A1) {
    const int n  = blockIdx.x;
    const int h  = threadIdx.x >> 5;
    const int l  = threadIdx.x & 31;

    const float2 q = *(const float2*)(Q + (long)n * D_ + h * DH_ + 2 * l);

    int rows[12];
    rows[0] = n;
    int cur = n ^ 1;
    rows[1] = cur;
#pragma unroll
    for (int lv = 1; lv < LVLS; lv++) {
        cur = ((cur >> 1) + N_) ^ 1;
        rows[lv + 1] = cur;
    }

    const long base = h * DH_ + 2 * l;

    float logit[12];
#pragma unroll
    for (int i = 0; i < 12; i++) {
        const __half2 kh = *(const __half2*)(Kh + base + (long)rows[i] * K1);
        const float2 kf = __half22float2(kh);
        float p = q.x * kf.x + q.y * kf.y;
#pragma unroll
        for (int off = 16; off; off >>= 1)
            p += __shfl_xor_sync(0xffffffffu, p, off);
        logit[i] = p * 0.125f;
    }

    float m = logit[0];
#pragma unroll
    for (int i = 1; i < 12; i++) m = fmaxf(m, logit[i]);
    float w[12], s = 0.f;
#pragma unroll
    for (int i = 0; i < 12; i++) { w[i] = __expf(logit[i] - m); s += w[i]; }
    const float inv = 1.f / s;

    float o0 = 0.f, o1 = 0.f;
#pragma unroll
    for (int i = 0; i < 12; i++) {
        const __half2 vh = *(const __half2*)(Vh + base + (long)rows[i] * K1);
        const float2 vf = __half22float2(vh);
        o0 += w[i] * vf.x;
        o1 += w[i] * vf.y;
    }
    o0 *= inv; o1 *= inv;

    *(__half2*)(A1 + (long)n * K1 + base) = __floats2half2_rn(o0, o1);
}

// ---------------- launch: 2-stream batch pipeline ----------------
extern "C" void kernel_launch(void* const* d_in, const int* in_sizes, int n_in,
                              void* d_out, int out_size) {
    const float* query = (const float*)d_in[0];
    const float* y  = (const float*)d_in[3];
    const float* Wq = (const float*)d_in[4];
    const float* Wk = (const float*)d_in[5];
    const float* Wv = (const float*)d_in[6];
    const float* Wo = (const float*)d_in[7];
    const float* bo = (const float*)d_in[8];
    float* out = (float*)d_out;

    __half *xy1, *w1, *a1, *Kh, *Vh;
    float *Qf;
    cudaGetSymbolAddress((void**)&xy1, g_xy1);
    cudaGetSymbolAddress((void**)&w1,  g_w1);
    cudaGetSymbolAddress((void**)&a1,  g_a1);
    cudaGetSymbolAddress((void**)&Qf,  g_Qf);
    cudaGetSymbolAddress((void**)&Kh,  g_Kh);
    cudaGetSymbolAddress((void**)&Vh,  g_Vh);
    __half* wq1 = w1;
    __half* wk1 = w1 + (long)D_ * K1;
    __half* wv1 = w1 + 2L * D_ * K1;
    __half* wo1 = w1 + 3L * D_ * K1;

    const int smQKV = SM_HALVES * 2;    // 110592
    const int smO   = SMO_HALVES * 2;   // 82944
    cudaFuncSetAttribute(hgemm_qkv, cudaFuncAttributeMaxDynamicSharedMemorySize, smQKV);
    cudaFuncSetAttribute(hgemm_o,   cudaFuncAttributeMaxDynamicSharedMemorySize, smO);

    build_all_kernel<<<dim3(128, 8), 256>>>(query, y, Wq, Wk, Wv, Wo);

    cudaEventRecord(g_hx.eFork, 0);
    cudaStreamWaitEvent(g_hx.s1, g_hx.eFork, 0);

    for (int b = 0; b < B_; b++) {
        cudaStream_t st = (b == 0) ? (cudaStream_t)0 : g_hx.s1;
        __half* xyb = xy1 + (long)b * XYR * K1;
        float*  Qb  = Qf  + (long)b * N_  * D_;
        __half* Kb  = Kh  + (long)b * XYR * D_;
        __half* Vb  = Vh  + (long)b * XYR * D_;
        __half* ab  = a1  + (long)b * N_  * K1;
        float*  ob  = out + (long)b * N_  * D_;

        hgemm_qkv<<<640, 256, smQKV, st>>>(xyb, wq1, wk1, wv1, Qb, Kb, Vb);
        attn_kernel<<<N_, 512, 0, st>>>(Qb, Kb, Vb, ab);
        hgemm_o<<<256, 256, smO, st>>>(ab, wo1, ob, bo);
    }

    cudaEventRecord(g_hx.eJoin, g_hx.s1);
    cudaStreamWaitEvent((cudaStream_t)0, g_hx.eJoin, 0);
}

// round 16
// speedup vs baseline: 1.0052x; 1.0052x over previous
#include <cuda_runtime.h>
#include <cuda_fp16.h>
#include <cstdint>

#define B_   2
#define N_   2048
#define D_   1024
#define H_   16
#define DH_  64
#define LVLS 11
#define XYR  4096            // padded rows per batch (4095 real + 1 zero)
#define K1   1024

// ---------------- scratch ----------------
__device__ __align__(16) __half g_xy1[(long)B_ * XYR * K1];
__device__ __align__(16) __half g_w1 [4][(long)D_ * K1];
__device__ __align__(16) __half g_a1 [(long)B_ * N_  * K1];
__device__ __align__(16) float  g_Qf [(long)B_ * N_  * D_];
__device__ __align__(16) __half g_Kh [(long)B_ * XYR * D_];
__device__ __align__(16) __half g_Vh [(long)B_ * XYR * D_];
__device__ __align__(16) float  g_Op0[(long)B_ * N_  * D_];   // O partial, k-half 0
__device__ __align__(16) float  g_Op1[(long)B_ * N_  * D_];   // O partial, k-half 1

// streams/events created once at load time, BEFORE harness mem checkpoints
struct HxStreams {
    cudaStream_t s1;
    cudaEvent_t eFork, eJoin;
    HxStreams() {
        int lo = 0, hi = 0;
        cudaDeviceGetStreamPriorityRange(&lo, &hi);
        cudaStreamCreateWithPriority(&s1, cudaStreamNonBlocking, lo);
        cudaEventCreateWithFlags(&eFork, cudaEventDisableTiming);
        cudaEventCreateWithFlags(&eJoin, cudaEventDisableTiming);
    }
};
static HxStreams g_hx;

__device__ __forceinline__ uint4 pack8(float4 a, float4 b) {
    __half2 h0 = __floats2half2_rn(a.x, a.y);
    __half2 h1 = __floats2half2_rn(a.z, a.w);
    __half2 h2 = __floats2half2_rn(b.x, b.y);
    __half2 h3 = __floats2half2_rn(b.z, b.w);
    uint4 u;
    u.x = *reinterpret_cast<uint32_t*>(&h0);
    u.y = *reinterpret_cast<uint32_t*>(&h1);
    u.z = *reinterpret_cast<uint32_t*>(&h2);
    u.w = *reinterpret_cast<uint32_t*>(&h3);
    return u;
}

// ---------------- fused prep: 4 weights + xy, one launch, 16B stores ----------------
__global__ void build_all_kernel(const float* __restrict__ q, const float* __restrict__ y,
                                 const float* __restrict__ W0, const float* __restrict__ W1,
                                 const float* __restrict__ W2, const float* __restrict__ W3) {
    const int slot = blockIdx.y;
    if (slot < 4) {
        const float* W;
        switch (slot) {
            case 0: W = W0; break;
            case 1: W = W1; break;
            case 2: W = W2; break;
            default: W = W3; break;
        }
        __half* out = g_w1[slot];
        const long total = (long)D_ * (D_ / 8);
        for (long i = (long)blockIdx.x * blockDim.x + threadIdx.x; i < total;
             i += (long)gridDim.x * blockDim.x) {
            int r = (int)(i >> 7);
            int c = ((int)i & 127) * 8;
            float4 v0 = *(const float4*)&W[(long)r * D_ + c];
            float4 v1 = *(const float4*)&W[(long)r * D_ + c + 4];
            *(uint4*)&out[(long)r * K1 + c] = pack8(v0, v1);
        }
    } else {
        const long quarter = (long)B_ * XYR * (D_ / 8) / 4;
        const long lo = (slot - 4) * quarter;
        const long hi = lo + quarter;
        for (long i = lo + (long)blockIdx.x * blockDim.x + threadIdx.x; i < hi;
             i += (long)gridDim.x * blockDim.x) {
            int r   = (int)(i >> 7);
            int c   = ((int)i & 127) * 8;
            int b   = r >> 12;
            int rr  = r & 4095;
            float4 v0 = make_float4(0.f, 0.f, 0.f, 0.f);
            float4 v1 = v0;
            if (rr < N_) {
                const float* src = &q[((long)(b * N_ + rr)) * D_ + c];
                v0 = *(const float4*)src;
                v1 = *(const float4*)(src + 4);
            } else if (rr < 4095) {
                const float* src = &y[((long)(b * (N_ - 1) + rr - N_)) * D_ + c];
                v0 = *(const float4*)src;
                v1 = *(const float4*)(src + 4);
            }
            *(uint4*)&g_xy1[(long)r * K1 + c] = pack8(v0, v1);
        }
    }
}

// ================ shared GEMM constants ================
#define KST  72
#define NCH (K1 / 64)                       // 16 chunks
#define SA_OFF(s) ((s) * (128 * KST))
#define SB_OFF(s) (3 * 128 * KST + (s) * (128 * KST))
#define SM_HALVES (6 * 128 * KST)           // 110592 B per CTA

// ---------------- QKV GEMM (frozen R10-R14 mainloop), 128x128 tiles ----------------
// One batch, 640 CTAs: [0,256) K, [256,512) V, [512,640) Q.
__global__ __launch_bounds__(256, 2)
void hgemm_qkv(const __half* __restrict__ Axy,
               const __half* __restrict__ wq, const __half* __restrict__ wk,
               const __half* __restrict__ wv,
               float* __restrict__ Qf, __half* __restrict__ Kh, __half* __restrict__ Vh) {
    extern __shared__ __half sm[];

    const __half* Bw;
    float* Cf = nullptr;
    __half* Ch = nullptr;
    bool halfOut = false;
    long row0, col0;
    {
        const int id = blockIdx.x;
        int bx, by;
        if (id < 256) {
            bx = id & 7; by = id >> 3;
            Bw = wk; Ch = Kh; halfOut = true;
        } else if (id < 512) {
            const int r = id - 256;
            bx = r & 7; by = r >> 3;
            Bw = wv; Ch = Vh; halfOut = true;
        } else {
            const int r = id - 512;
            bx = r & 7; by = r >> 3;
            Bw = wq; Cf = Qf;
        }
        row0 = (long)by * 128;
        col0 = (long)bx * 128;
    }

    const int tid  = threadIdx.x;
    const int lane = tid & 31;
    const int warp = tid >> 5;
    const int wm0  = (warp & 1) * 64;
    const int wn0  = (warp >> 1) * 32;

    float acc[4][4][4];
#pragma unroll
    for (int mt = 0; mt < 4; mt++)
#pragma unroll
        for (int nt = 0; nt < 4; nt++)
#pragma unroll
            for (int i = 0; i < 4; i++) acc[mt][nt][i] = 0.f;

    const int aoff = (wm0 + (lane & 15)) * KST + (lane >> 4) * 8;
    const int boff = (wn0 + (lane >> 4) * 8 + (lane & 7)) * KST + ((lane >> 3) & 1) * 8;

    const __half* Abase = Axy + row0 * K1;
    const __half* Bbase = Bw + col0 * K1;

    auto ld_tile = [&](int s, int c) {
        const long k0 = (long)c * 64;
#pragma unroll
        for (int t = 0; t < 4; t++) {
            const int i = tid + t * 256;
            const long r = i >> 3;
            const long cc = (i & 7) * 8;
            uint32_t dst = (uint32_t)__cvta_generic_to_shared(
                &sm[SA_OFF(s) + (int)r * KST + (int)cc]);
            const __half* src = Abase + r * K1 + k0 + cc;
            asm volatile("cp.async.cg.shared.global [%0], [%1], 16;" :: "r"(dst), "l"(src));
        }
#pragma unroll
        for (int t = 0; t < 4; t++) {
            const int i = tid + t * 256;
            const long r = i >> 3;
            const long cc = (i & 7) * 8;
            uint32_t dst = (uint32_t)__cvta_generic_to_shared(
                &sm[SB_OFF(s) + (int)r * KST + (int)cc]);
            const __half* src = Bbase + r * K1 + k0 + cc;
            asm volatile("cp.async.cg.shared.global [%0], [%1], 16;" :: "r"(dst), "l"(src));
        }
    };

    ld_tile(0, 0); asm volatile("cp.async.commit_group;" ::: "memory");
    ld_tile(1, 1); asm volatile("cp.async.commit_group;" ::: "memory");

    for (int c = 0; c < NCH; c++) {
        asm volatile("cp.async.wait_group 1;" ::: "memory");
        __syncthreads();
        if (c + 2 < NCH) ld_tile((c + 2) % 3, c + 2);
        asm volatile("cp.async.commit_group;" ::: "memory");

        const int buf = c % 3;
#pragma unroll
        for (int ks = 0; ks < 4; ks++) {
            uint32_t fa[4][4];
#pragma unroll
            for (int mt = 0; mt < 4; mt++) {
                uint32_t ad = (uint32_t)__cvta_generic_to_shared(
                    &sm[SA_OFF(buf) + aoff + mt * 16 * KST + ks * 16]);
                asm volatile("ldmatrix.sync.aligned.m8n8.x4.shared.b16 {%0,%1,%2,%3}, [%4];\n"
                             : "=r"(fa[mt][0]), "=r"(fa[mt][1]),
                               "=r"(fa[mt][2]), "=r"(fa[mt][3])
                             : "r"(ad));
            }
            uint32_t fb[4][2];
#pragma unroll
            for (int np = 0; np < 2; np++) {
                uint32_t bd = (uint32_t)__cvta_generic_to_shared(
                    &sm[SB_OFF(buf) + boff + np * 16 * KST + ks * 16]);
                uint32_t r0, r1, r2, r3;
                asm volatile("ldmatrix.sync.aligned.m8n8.x4.shared.b16 {%0,%1,%2,%3}, [%4];\n"
                             : "=r"(r0), "=r"(r1), "=r"(r2), "=r"(r3) : "r"(bd));
                fb[np * 2][0] = r0; fb[np * 2][1] = r1;
                fb[np * 2 + 1][0] = r2; fb[np * 2 + 1][1] = r3;
            }
#pragma unroll
            for (int mt = 0; mt < 4; mt++)
#pragma unroll
                for (int nt = 0; nt < 4; nt++) {
                    asm volatile(
                        "mma.sync.aligned.m16n8k16.row.col.f32.f16.f16.f32 "
                        "{%0,%1,%2,%3},{%4,%5,%6,%7},{%8,%9},{%0,%1,%2,%3};\n"
                        : "+f"(acc[mt][nt][0]), "+f"(acc[mt][nt][1]),
                          "+f"(acc[mt][nt][2]), "+f"(acc[mt][nt][3])
                        : "r"(fa[mt][0]), "r"(fa[mt][1]),
                          "r"(fa[mt][2]), "r"(fa[mt][3]),
                          "r"(fb[nt][0]), "r"(fb[nt][1]));
                }
        }
    }

#pragma unroll
    for (int mt = 0; mt < 4; mt++)
#pragma unroll
        for (int nt = 0; nt < 4; nt++) {
            long r = row0 + wm0 + mt * 16 + (lane >> 2);
            long cc = col0 + wn0 + nt * 8 + (lane & 3) * 2;
            if (halfOut) {
                *(__half2*)&Ch[r * D_ + cc] =
                    __floats2half2_rn(acc[mt][nt][0], acc[mt][nt][1]);
                *(__half2*)&Ch[(r + 8) * D_ + cc] =
                    __floats2half2_rn(acc[mt][nt][2], acc[mt][nt][3]);
            } else {
                *(float2*)&Cf[r * D_ + cc] =
                    make_float2(acc[mt][nt][0], acc[mt][nt][1]);
                *(float2*)&Cf[(r + 8) * D_ + cc] =
                    make_float2(acc[mt][nt][2], acc[mt][nt][3]);
            }
        }
}

// ---------------- O GEMM: split-K=2, 128x128 tiles, 256 CTAs per batch ----------------
// Same frozen mainloop/warptile as QKV; CTA id>>7 selects k-half (8 chunks);
// partial fp32 written to P (no bias). Deterministic fixed split.
__global__ __launch_bounds__(256, 2)
void hgemm_o_sk(const __half* __restrict__ Aatt, const __half* __restrict__ wo,
                float* __restrict__ P0, float* __restrict__ P1) {
    extern __shared__ __half sm[];

    const int id = blockIdx.x;
    const int kk = id >> 7;                 // 0 or 1
    const int t  = id & 127;
    const int bx = t & 7, by = t >> 3;
    const long row0 = (long)by * 128;
    const long col0 = (long)bx * 128;
    float* P = kk ? P1 : P0;
    const int cbase = kk * 8;               // chunk range [cbase, cbase+8)

    const int tid  = threadIdx.x;
    const int lane = tid & 31;
    const int warp = tid >> 5;
    const int wm0  = (warp & 1) * 64;
    const int wn0  = (warp >> 1) * 32;

    float acc[4][4][4];
#pragma unroll
    for (int mt = 0; mt < 4; mt++)
#pragma unroll
        for (int nt = 0; nt < 4; nt++)
#pragma unroll
            for (int i = 0; i < 4; i++) acc[mt][nt][i] = 0.f;

    const int aoff = (wm0 + (lane & 15)) * KST + (lane >> 4) * 8;
    const int boff = (wn0 + (lane >> 4) * 8 + (lane & 7)) * KST + ((lane >> 3) & 1) * 8;

    const __half* Abase = Aatt + row0 * K1;
    const __half* Bbase = wo + col0 * K1;

    auto ld_tile = [&](int s, int c) {
        const long k0 = (long)(cbase + c) * 64;
#pragma unroll
        for (int t2 = 0; t2 < 4; t2++) {
            const int i = tid + t2 * 256;
            const long r = i >> 3;
            const long cc = (i & 7) * 8;
            uint32_t dst = (uint32_t)__cvta_generic_to_shared(
                &sm[SA_OFF(s) + (int)r * KST + (int)cc]);
            const __half* src = Abase + r * K1 + k0 + cc;
            asm volatile("cp.async.cg.shared.global [%0], [%1], 16;" :: "r"(dst), "l"(src));
        }
#pragma unroll
        for (int t2 = 0; t2 < 4; t2++) {
            const int i = tid + t2 * 256;
            const long r = i >> 3;
            const long cc = (i & 7) * 8;
            uint32_t dst = (uint32_t)__cvta_generic_to_shared(
                &sm[SB_OFF(s) + (int)r * KST + (int)cc]);
            const __half* src = Bbase + r * K1 + k0 + cc;
            asm volatile("cp.async.cg.shared.global [%0], [%1], 16;" :: "r"(dst), "l"(src));
        }
    };

    ld_tile(0, 0); asm volatile("cp.async.commit_group;" ::: "memory");
    ld_tile(1, 1); asm volatile("cp.async.commit_group;" ::: "memory");

    for (int c = 0; c < 8; c++) {
        asm volatile("cp.async.wait_group 1;" ::: "memory");
        __syncthreads();
        if (c + 2 < 8) ld_tile((c + 2) % 3, c + 2);
        asm volatile("cp.async.commit_group;" ::: "memory");

        const int buf = c % 3;
#pragma unroll
        for (int ks = 0; ks < 4; ks++) {
            uint32_t fa[4][4];
#pragma unroll
            for (int mt = 0; mt < 4; mt++) {
                uint32_t ad = (uint32_t)__cvta_generic_to_shared(
                    &sm[SA_OFF(buf) + aoff + mt * 16 * KST + ks * 16]);
                asm volatile("ldmatrix.sync.aligned.m8n8.x4.shared.b16 {%0,%1,%2,%3}, [%4];\n"
                             : "=r"(fa[mt][0]), "=r"(fa[mt][1]),
                               "=r"(fa[mt][2]), "=r"(fa[mt][3])
                             : "r"(ad));
            }
            uint32_t fb[4][2];
#pragma unroll
            for (int np = 0; np < 2; np++) {
                uint32_t bd = (uint32_t)__cvta_generic_to_shared(
                    &sm[SB_OFF(buf) + boff + np * 16 * KST + ks * 16]);
                uint32_t r0, r1, r2, r3;
                asm volatile("ldmatrix.sync.aligned.m8n8.x4.shared.b16 {%0,%1,%2,%3}, [%4];\n"
                             : "=r"(r0), "=r"(r1), "=r"(r2), "=r"(r3) : "r"(bd));
                fb[np * 2][0] = r0; fb[np * 2][1] = r1;
                fb[np * 2 + 1][0] = r2; fb[np * 2 + 1][1] = r3;
            }
#pragma unroll
            for (int mt = 0; mt < 4; mt++)
#pragma unroll
                for (int nt = 0; nt < 4; nt++) {
                    asm volatile(
                        "mma.sync.aligned.m16n8k16.row.col.f32.f16.f16.f32 "
                        "{%0,%1,%2,%3},{%4,%5,%6,%7},{%8,%9},{%0,%1,%2,%3};\n"
                        : "+f"(acc[mt][nt][0]), "+f"(acc[mt][nt][1]),
                          "+f"(acc[mt][nt][2]), "+f"(acc[mt][nt][3])
                        : "r"(fa[mt][0]), "r"(fa[mt][1]),
                          "r"(fa[mt][2]), "r"(fa[mt][3]),
                          "r"(fb[nt][0]), "r"(fb[nt][1]));
                }
        }
    }

#pragma unroll
    for (int mt = 0; mt < 4; mt++)
#pragma unroll
        for (int nt = 0; nt < 4; nt++) {
            long r = row0 + wm0 + mt * 16 + (lane >> 2);
            long cc = col0 + wn0 + nt * 8 + (lane & 3) * 2;
            *(float2*)&P[r * D_ + cc] =
                make_float2(acc[mt][nt][0], acc[mt][nt][1]);
            *(float2*)&P[(r + 8) * D_ + cc] =
                make_float2(acc[mt][nt][2], acc[mt][nt][3]);
        }
}

// ---------------- split-K reduce: out = p0 + p1 + bias ----------------
__global__ void reduce_o(const float* __restrict__ p0, const float* __restrict__ p1,
                         const float* __restrict__ bias, float* __restrict__ out) {
    const long total = (long)N_ * D_ / 4;
    for (long i = (long)blockIdx.x * blockDim.x + threadIdx.x; i < total;
         i += (long)gridDim.x * blockDim.x) {
        const long e = i * 4;
        const int col = (int)(e & (D_ - 1));
        float4 a = *(const float4*)&p0[e];
        float4 b = *(const float4*)&p1[e];
        float4 bb = *(const float4*)&bias[col];
        float4 v;
        v.x = a.x + b.x + bb.x;
        v.y = a.y + b.y + bb.y;
        v.z = a.z + b.z + bb.z;
        v.w = a.w + b.w + bb.w;
        *(float4*)&out[e] = v;
    }
}

// ---------------- hierarchical sparse attention (per-batch, fp16 K/V) ----------------
__global__ __launch_bounds__(512)
void attn_kernel(const float* __restrict__ Q, const __half* __restrict__ Kh,
                 const __half* __restrict__ Vh, __half* __restrict__ A1) {
    const int n  = blockIdx.x;
    const int h  = threadIdx.x >> 5;
    const int l  = threadIdx.x & 31;

    const float2 q = *(const float2*)(Q + (long)n * D_ + h * DH_ + 2 * l);

    int rows[12];
    rows[0] = n;
    int cur = n ^ 1;
    rows[1] = cur;
#pragma unroll
    for (int lv = 1; lv < LVLS; lv++) {
        cur = ((cur >> 1) + N_) ^ 1;
        rows[lv + 1] = cur;
    }

    const long base = h * DH_ + 2 * l;

    float logit[12];
#pragma unroll
    for (int i = 0; i < 12; i++) {
        const __half2 kh = *(const __half2*)(Kh + base + (long)rows[i] * K1);
        const float2 kf = __half22float2(kh);
        float p = q.x * kf.x + q.y * kf.y;
#pragma unroll
        for (int off = 16; off; off >>= 1)
            p += __shfl_xor_sync(0xffffffffu, p, off);
        logit[i] = p * 0.125f;
    }

    float m = logit[0];
#pragma unroll
    for (int i = 1; i < 12; i++) m = fmaxf(m, logit[i]);
    float w[12], s = 0.f;
#pragma unroll
    for (int i = 0; i < 12; i++) { w[i] = __expf(logit[i] - m); s += w[i]; }
    const float inv = 1.f / s;

    float o0 = 0.f, o1 = 0.f;
#pragma unroll
    for (int i = 0; i < 12; i++) {
        const __half2 vh = *(const __half2*)(Vh + base + (long)rows[i] * K1);
        const float2 vf = __half22float2(vh);
        o0 += w[i] * vf.x;
        o1 += w[i] * vf.y;
    }
    o0 *= inv; o1 *= inv;

    *(__half2*)(A1 + (long)n * K1 + base) = __floats2half2_rn(o0, o1);
}

// ---------------- launch: 2-stream batch pipeline ----------------
extern "C" void kernel_launch(void* const* d_in, const int* in_sizes, int n_in,
                              void* d_out, int out_size) {
    const float* query = (const float*)d_in[0];
    const float* y  = (const float*)d_in[3];
    const float* Wq = (const float*)d_in[4];
    const float* Wk = (const float*)d_in[5];
    const float* Wv = (const float*)d_in[6];
    const float* Wo = (const float*)d_in[7];
    const float* bo = (const float*)d_in[8];
    float* out = (float*)d_out;

    __half *xy1, *w1, *a1, *Kh, *Vh;
    float *Qf, *Op0, *Op1;
    cudaGetSymbolAddress((void**)&xy1, g_xy1);
    cudaGetSymbolAddress((void**)&w1,  g_w1);
    cudaGetSymbolAddress((void**)&a1,  g_a1);
    cudaGetSymbolAddress((void**)&Qf,  g_Qf);
    cudaGetSymbolAddress((void**)&Kh,  g_Kh);
    cudaGetSymbolAddress((void**)&Vh,  g_Vh);
    cudaGetSymbolAddress((void**)&Op0, g_Op0);
    cudaGetSymbolAddress((void**)&Op1, g_Op1);
    __half* wq1 = w1;
    __half* wk1 = w1 + (long)D_ * K1;
    __half* wv1 = w1 + 2L * D_ * K1;
    __half* wo1 = w1 + 3L * D_ * K1;

    const int smbytes = SM_HALVES * 2;   // 110592
    cudaFuncSetAttribute(hgemm_qkv,  cudaFuncAttributeMaxDynamicSharedMemorySize, smbytes);
    cudaFuncSetAttribute(hgemm_o_sk, cudaFuncAttributeMaxDynamicSharedMemorySize, smbytes);

    build_all_kernel<<<dim3(128, 8), 256>>>(query, y, Wq, Wk, Wv, Wo);

    cudaEventRecord(g_hx.eFork, 0);
    cudaStreamWaitEvent(g_hx.s1, g_hx.eFork, 0);

    for (int b = 0; b < B_; b++) {
        cudaStream_t st = (b == 0) ? (cudaStream_t)0 : g_hx.s1;
        __half* xyb = xy1 + (long)b * XYR * K1;
        float*  Qb  = Qf  + (long)b * N_  * D_;
        __half* Kb  = Kh  + (long)b * XYR * D_;
        __half* Vb  = Vh  + (long)b * XYR * D_;
        __half* ab  = a1  + (long)b * N_  * K1;
        float*  p0b = Op0 + (long)b * N_  * D_;
        float*  p1b = Op1 + (long)b * N_  * D_;
        float*  ob  = out + (long)b * N_  * D_;

        hgemm_qkv<<<640, 256, smbytes, st>>>(xyb, wq1, wk1, wv1, Qb, Kb, Vb);
        attn_kernel<<<N_, 512, 0, st>>>(Qb, Kb, Vb, ab);
        hgemm_o_sk<<<256, 256, smbytes, st>>>(ab, wo1, p0b, p1b);
        reduce_o<<<512, 256, 0, st>>>(p0b, p1b, bo, ob);
    }

    cudaEventRecord(g_hx.eJoin, g_hx.s1);
    cudaStreamWaitEvent((cudaStream_t)0, g_hx.eJoin, 0);
}

// round 17
// speedup vs baseline: 1.0190x; 1.0138x over previous
#include <cuda_runtime.h>
#include <cuda_fp16.h>
#include <cstdint>

#define B_   2
#define N_   2048
#define D_   1024
#define H_   16
#define DH_  64
#define LVLS 11
#define XYR  4096            // padded rows per batch (4095 real + 1 zero)
#define K1   1024

// ---------------- scratch ----------------
__device__ __align__(16) __half g_xy1[(long)B_ * XYR * K1];
__device__ __align__(16) __half g_w1 [4][(long)D_ * K1];
__device__ __align__(16) __half g_a1 [(long)B_ * N_  * K1];
__device__ __align__(16) float  g_Qf [(long)B_ * N_  * D_];
__device__ __align__(16) __half g_Kh [(long)B_ * XYR * D_];
__device__ __align__(16) __half g_Vh [(long)B_ * XYR * D_];

// streams/events created once at load time, BEFORE harness mem checkpoints
struct HxStreams {
    cudaStream_t s1;
    cudaEvent_t eFork, eJoin;
    HxStreams() {
        int lo = 0, hi = 0;
        cudaDeviceGetStreamPriorityRange(&lo, &hi);
        cudaStreamCreateWithPriority(&s1, cudaStreamNonBlocking, lo);
        cudaEventCreateWithFlags(&eFork, cudaEventDisableTiming);
        cudaEventCreateWithFlags(&eJoin, cudaEventDisableTiming);
    }
};
static HxStreams g_hx;

__device__ __forceinline__ uint4 pack8(float4 a, float4 b) {
    __half2 h0 = __floats2half2_rn(a.x, a.y);
    __half2 h1 = __floats2half2_rn(a.z, a.w);
    __half2 h2 = __floats2half2_rn(b.x, b.y);
    __half2 h3 = __floats2half2_rn(b.z, b.w);
    uint4 u;
    u.x = *reinterpret_cast<uint32_t*>(&h0);
    u.y = *reinterpret_cast<uint32_t*>(&h1);
    u.z = *reinterpret_cast<uint32_t*>(&h2);
    u.w = *reinterpret_cast<uint32_t*>(&h3);
    return u;
}

// ---------------- fused prep: 4 weights + xy, one launch, 16B stores ----------------
__global__ void build_all_kernel(const float* __restrict__ q, const float* __restrict__ y,
                                 const float* __restrict__ W0, const float* __restrict__ W1,
                                 const float* __restrict__ W2, const float* __restrict__ W3) {
    const int slot = blockIdx.y;
    if (slot < 4) {
        const float* W;
        switch (slot) {
            case 0: W = W0; break;
            case 1: W = W1; break;
            case 2: W = W2; break;
            default: W = W3; break;
        }
        __half* out = g_w1[slot];
        const long total = (long)D_ * (D_ / 8);
        for (long i = (long)blockIdx.x * blockDim.x + threadIdx.x; i < total;
             i += (long)gridDim.x * blockDim.x) {
            int r = (int)(i >> 7);
            int c = ((int)i & 127) * 8;
            float4 v0 = *(const float4*)&W[(long)r * D_ + c];
            float4 v1 = *(const float4*)&W[(long)r * D_ + c + 4];
            *(uint4*)&out[(long)r * K1 + c] = pack8(v0, v1);
        }
    } else {
        const long quarter = (long)B_ * XYR * (D_ / 8) / 4;
        const long lo = (slot - 4) * quarter;
        const long hi = lo + quarter;
        for (long i = lo + (long)blockIdx.x * blockDim.x + threadIdx.x; i < hi;
             i += (long)gridDim.x * blockDim.x) {
            int r   = (int)(i >> 7);
            int c   = ((int)i & 127) * 8;
            int b   = r >> 12;
            int rr  = r & 4095;
            float4 v0 = make_float4(0.f, 0.f, 0.f, 0.f);
            float4 v1 = v0;
            if (rr < N_) {
                const float* src = &q[((long)(b * N_ + rr)) * D_ + c];
                v0 = *(const float4*)src;
                v1 = *(const float4*)(src + 4);
            } else if (rr < 4095) {
                const float* src = &y[((long)(b * (N_ - 1) + rr - N_)) * D_ + c];
                v0 = *(const float4*)src;
                v1 = *(const float4*)(src + 4);
            }
            *(uint4*)&g_xy1[(long)r * K1 + c] = pack8(v0, v1);
        }
    }
}

// ================ shared GEMM constants ================
#define KST  72
#define NCH (K1 / 64)                       // 16 chunks
#define SA_OFF(s) ((s) * (128 * KST))
#define SB_OFF(s) (3 * 128 * KST + (s) * (128 * KST))
#define SM_HALVES (6 * 128 * KST)           // 110592 B per CTA

// ---------------- QKV GEMM (frozen R10-R14 mainloop), 128x128 tiles ----------------
// One batch, 640 CTAs: [0,256) K, [256,512) V, [512,640) Q.
__global__ __launch_bounds__(256, 2)
void hgemm_qkv(const __half* __restrict__ Axy,
               const __half* __restrict__ wq, const __half* __restrict__ wk,
               const __half* __restrict__ wv,
               float* __restrict__ Qf, __half* __restrict__ Kh, __half* __restrict__ Vh) {
    extern __shared__ __half sm[];

    const __half* Bw;
    float* Cf = nullptr;
    __half* Ch = nullptr;
    bool halfOut = false;
    long row0, col0;
    {
        const int id = blockIdx.x;
        int bx, by;
        if (id < 256) {
            bx = id & 7; by = id >> 3;
            Bw = wk; Ch = Kh; halfOut = true;
        } else if (id < 512) {
            const int r = id - 256;
            bx = r & 7; by = r >> 3;
            Bw = wv; Ch = Vh; halfOut = true;
        } else {
            const int r = id - 512;
            bx = r & 7; by = r >> 3;
            Bw = wq; Cf = Qf;
        }
        row0 = (long)by * 128;
        col0 = (long)bx * 128;
    }

    const int tid  = threadIdx.x;
    const int lane = tid & 31;
    const int warp = tid >> 5;
    const int wm0  = (warp & 1) * 64;
    const int wn0  = (warp >> 1) * 32;

    float acc[4][4][4];
#pragma unroll
    for (int mt = 0; mt < 4; mt++)
#pragma unroll
        for (int nt = 0; nt < 4; nt++)
#pragma unroll
            for (int i = 0; i < 4; i++) acc[mt][nt][i] = 0.f;

    const int aoff = (wm0 + (lane & 15)) * KST + (lane >> 4) * 8;
    const int boff = (wn0 + (lane >> 4) * 8 + (lane & 7)) * KST + ((lane >> 3) & 1) * 8;

    const __half* Abase = Axy + row0 * K1;
    const __half* Bbase = Bw + col0 * K1;

    auto ld_tile = [&](int s, int c) {
        const long k0 = (long)c * 64;
#pragma unroll
        for (int t = 0; t < 4; t++) {
            const int i = tid + t * 256;
            const long r = i >> 3;
            const long cc = (i & 7) * 8;
            uint32_t dst = (uint32_t)__cvta_generic_to_shared(
                &sm[SA_OFF(s) + (int)r * KST + (int)cc]);
            const __half* src = Abase + r * K1 + k0 + cc;
            asm volatile("cp.async.cg.shared.global [%0], [%1], 16;" :: "r"(dst), "l"(src));
        }
#pragma unroll
        for (int t = 0; t < 4; t++) {
            const int i = tid + t * 256;
            const long r = i >> 3;
            const long cc = (i & 7) * 8;
            uint32_t dst = (uint32_t)__cvta_generic_to_shared(
                &sm[SB_OFF(s) + (int)r * KST + (int)cc]);
            const __half* src = Bbase + r * K1 + k0 + cc;
            asm volatile("cp.async.cg.shared.global [%0], [%1], 16;" :: "r"(dst), "l"(src));
        }
    };

    ld_tile(0, 0); asm volatile("cp.async.commit_group;" ::: "memory");
    ld_tile(1, 1); asm volatile("cp.async.commit_group;" ::: "memory");

    for (int c = 0; c < NCH; c++) {
        asm volatile("cp.async.wait_group 1;" ::: "memory");
        __syncthreads();
        if (c + 2 < NCH) ld_tile((c + 2) % 3, c + 2);
        asm volatile("cp.async.commit_group;" ::: "memory");

        const int buf = c % 3;
#pragma unroll
        for (int ks = 0; ks < 4; ks++) {
            uint32_t fa[4][4];
#pragma unroll
            for (int mt = 0; mt < 4; mt++) {
                uint32_t ad = (uint32_t)__cvta_generic_to_shared(
                    &sm[SA_OFF(buf) + aoff + mt * 16 * KST + ks * 16]);
                asm volatile("ldmatrix.sync.aligned.m8n8.x4.shared.b16 {%0,%1,%2,%3}, [%4];\n"
                             : "=r"(fa[mt][0]), "=r"(fa[mt][1]),
                               "=r"(fa[mt][2]), "=r"(fa[mt][3])
                             : "r"(ad));
            }
            uint32_t fb[4][2];
#pragma unroll
            for (int np = 0; np < 2; np++) {
                uint32_t bd = (uint32_t)__cvta_generic_to_shared(
                    &sm[SB_OFF(buf) + boff + np * 16 * KST + ks * 16]);
                uint32_t r0, r1, r2, r3;
                asm volatile("ldmatrix.sync.aligned.m8n8.x4.shared.b16 {%0,%1,%2,%3}, [%4];\n"
                             : "=r"(r0), "=r"(r1), "=r"(r2), "=r"(r3) : "r"(bd));
                fb[np * 2][0] = r0; fb[np * 2][1] = r1;
                fb[np * 2 + 1][0] = r2; fb[np * 2 + 1][1] = r3;
            }
#pragma unroll
            for (int mt = 0; mt < 4; mt++)
#pragma unroll
                for (int nt = 0; nt < 4; nt++) {
                    asm volatile(
                        "mma.sync.aligned.m16n8k16.row.col.f32.f16.f16.f32 "
                        "{%0,%1,%2,%3},{%4,%5,%6,%7},{%8,%9},{%0,%1,%2,%3};\n"
                        : "+f"(acc[mt][nt][0]), "+f"(acc[mt][nt][1]),
                          "+f"(acc[mt][nt][2]), "+f"(acc[mt][nt][3])
                        : "r"(fa[mt][0]), "r"(fa[mt][1]),
                          "r"(fa[mt][2]), "r"(fa[mt][3]),
                          "r"(fb[nt][0]), "r"(fb[nt][1]));
                }
        }
    }

#pragma unroll
    for (int mt = 0; mt < 4; mt++)
#pragma unroll
        for (int nt = 0; nt < 4; nt++) {
            long r = row0 + wm0 + mt * 16 + (lane >> 2);
            long cc = col0 + wn0 + nt * 8 + (lane & 3) * 2;
            if (halfOut) {
                *(__half2*)&Ch[r * D_ + cc] =
                    __floats2half2_rn(acc[mt][nt][0], acc[mt][nt][1]);
                *(__half2*)&Ch[(r + 8) * D_ + cc] =
                    __floats2half2_rn(acc[mt][nt][2], acc[mt][nt][3]);
            } else {
                *(float2*)&Cf[r * D_ + cc] =
                    make_float2(acc[mt][nt][0], acc[mt][nt][1]);
                *(float2*)&Cf[(r + 8) * D_ + cc] =
                    make_float2(acc[mt][nt][2], acc[mt][nt][3]);
            }
        }
}

// ---------------- O GEMM: 64x128 tiles, 128 threads, 256 CTAs per batch ----------------
// 4 warps as 1(M)x4(N); warptile 64x32 and K-sequence identical to QKV (frozen).
// A (64 rows) replicated across 4 warps, B split 4 ways. Full bias epilogue.
#define OA_OFF(s) ((s) * (64 * KST))
#define OB_OFF(s) (3 * 64 * KST + (s) * (128 * KST))
#define SMO_HALVES (3 * 64 * KST + 3 * 128 * KST)   // 41472 halves = 82944 B

__global__ __launch_bounds__(128, 2)
void hgemm_o(const __half* __restrict__ Aatt, const __half* __restrict__ wo,
             float* __restrict__ Out, const float* __restrict__ bias) {
    extern __shared__ __half sm[];

    const int id = blockIdx.x;
    const int bx = id & 7, by = id >> 3;        // 32 row blocks x 8 col blocks
    const long row0 = (long)by * 64;
    const long col0 = (long)bx * 128;

    const int tid  = threadIdx.x;
    const int lane = tid & 31;
    const int warp = tid >> 5;
    const int wn0  = warp * 32;                 // 4 warps along N

    float acc[4][4][4];
#pragma unroll
    for (int mt = 0; mt < 4; mt++)
#pragma unroll
        for (int nt = 0; nt < 4; nt++)
#pragma unroll
            for (int i = 0; i < 4; i++) acc[mt][nt][i] = 0.f;

    const int aoff = (lane & 15) * KST + (lane >> 4) * 8;                    // wm0 = 0
    const int boff = (wn0 + (lane >> 4) * 8 + (lane & 7)) * KST + ((lane >> 3) & 1) * 8;

    const __half* Abase = Aatt + row0 * K1;
    const __half* Bbase = wo + col0 * K1;

    auto ld_tile = [&](int s, int c) {
        const long k0 = (long)c * 64;
#pragma unroll
        for (int t = 0; t < 4; t++) {          // A: 64 rows x 128B, 128 threads
            const int i = tid + t * 128;
            const long r = i >> 3;
            const long cc = (i & 7) * 8;
            uint32_t dst = (uint32_t)__cvta_generic_to_shared(
                &sm[OA_OFF(s) + (int)r * KST + (int)cc]);
            const __half* src = Abase + r * K1 + k0 + cc;
            asm volatile("cp.async.cg.shared.global [%0], [%1], 16;" :: "r"(dst), "l"(src));
        }
#pragma unroll
        for (int t = 0; t < 8; t++) {          // B: 128 rows x 128B
            const int i = tid + t * 128;
            const long r = i >> 3;
            const long cc = (i & 7) * 8;
            uint32_t dst = (uint32_t)__cvta_generic_to_shared(
                &sm[OB_OFF(s) + (int)r * KST + (int)cc]);
            const __half* src = Bbase + r * K1 + k0 + cc;
            asm volatile("cp.async.cg.shared.global [%0], [%1], 16;" :: "r"(dst), "l"(src));
        }
    };

    ld_tile(0, 0); asm volatile("cp.async.commit_group;" ::: "memory");
    ld_tile(1, 1); asm volatile("cp.async.commit_group;" ::: "memory");

    for (int c = 0; c < NCH; c++) {
        asm volatile("cp.async.wait_group 1;" ::: "memory");
        __syncthreads();
        if (c + 2 < NCH) ld_tile((c + 2) % 3, c + 2);
        asm volatile("cp.async.commit_group;" ::: "memory");

        const int buf = c % 3;
#pragma unroll
        for (int ks = 0; ks < 4; ks++) {
            uint32_t fa[4][4];
#pragma unroll
            for (int mt = 0; mt < 4; mt++) {
                uint32_t ad = (uint32_t)__cvta_generic_to_shared(
                    &sm[OA_OFF(buf) + aoff + mt * 16 * KST + ks * 16]);
                asm volatile("ldmatrix.sync.aligned.m8n8.x4.shared.b16 {%0,%1,%2,%3}, [%4];\n"
                             : "=r"(fa[mt][0]), "=r"(fa[mt][1]),
                               "=r"(fa[mt][2]), "=r"(fa[mt][3])
                             : "r"(ad));
            }
            uint32_t fb[4][2];
#pragma unroll
            for (int np = 0; np < 2; np++) {
                uint32_t bd = (uint32_t)__cvta_generic_to_shared(
                    &sm[OB_OFF(buf) + boff + np * 16 * KST + ks * 16]);
                uint32_t r0, r1, r2, r3;
                asm volatile("ldmatrix.sync.aligned.m8n8.x4.shared.b16 {%0,%1,%2,%3}, [%4];\n"
                             : "=r"(r0), "=r"(r1), "=r"(r2), "=r"(r3) : "r"(bd));
                fb[np * 2][0] = r0; fb[np * 2][1] = r1;
                fb[np * 2 + 1][0] = r2; fb[np * 2 + 1][1] = r3;
            }
#pragma unroll
            for (int mt = 0; mt < 4; mt++)
#pragma unroll
                for (int nt = 0; nt < 4; nt++) {
                    asm volatile(
                        "mma.sync.aligned.m16n8k16.row.col.f32.f16.f16.f32 "
                        "{%0,%1,%2,%3},{%4,%5,%6,%7},{%8,%9},{%0,%1,%2,%3};\n"
                        : "+f"(acc[mt][nt][0]), "+f"(acc[mt][nt][1]),
                          "+f"(acc[mt][nt][2]), "+f"(acc[mt][nt][3])
                        : "r"(fa[mt][0]), "r"(fa[mt][1]),
                          "r"(fa[mt][2]), "r"(fa[mt][3]),
                          "r"(fb[nt][0]), "r"(fb[nt][1]));
                }
        }
    }

#pragma unroll
    for (int mt = 0; mt < 4; mt++)
#pragma unroll
        for (int nt = 0; nt < 4; nt++) {
            long r = row0 + mt * 16 + (lane >> 2);
            long cc = col0 + wn0 + nt * 8 + (lane & 3) * 2;
            float2 v0 = make_float2(acc[mt][nt][0], acc[mt][nt][1]);
            float2 v1 = make_float2(acc[mt][nt][2], acc[mt][nt][3]);
            float2 bb = *(const float2*)&bias[cc];
            v0.x += bb.x; v0.y += bb.y; v1.x += bb.x; v1.y += bb.y;
            *(float2*)&Out[r * D_ + cc]       = v0;
            *(float2*)&Out[(r + 8) * D_ + cc] = v1;
        }
}

// ---------------- hierarchical sparse attention (per-batch, fp16 K/V) ----------------
__global__ __launch_bounds__(512)
void attn_kernel(const float* __restrict__ Q, const __half* __restrict__ Kh,
                 const __half* __restrict__ Vh, __half* __restrict__ A1) {
    const int n  = blockIdx.x;
    const int h  = threadIdx.x >> 5;
    const int l  = threadIdx.x & 31;

    const float2 q = *(const float2*)(Q + (long)n * D_ + h * DH_ + 2 * l);

    int rows[12];
    rows[0] = n;
    int cur = n ^ 1;
    rows[1] = cur;
#pragma unroll
    for (int lv = 1; lv < LVLS; lv++) {
        cur = ((cur >> 1) + N_) ^ 1;
        rows[lv + 1] = cur;
    }

    const long base = h * DH_ + 2 * l;

    float logit[12];
#pragma unroll
    for (int i = 0; i < 12; i++) {
        const __half2 kh = *(const __half2*)(Kh + base + (long)rows[i] * K1);
        const float2 kf = __half22float2(kh);
        float p = q.x * kf.x + q.y * kf.y;
#pragma unroll
        for (int off = 16; off; off >>= 1)
            p += __shfl_xor_sync(0xffffffffu, p, off);
        logit[i] = p * 0.125f;
    }

    float m = logit[0];
#pragma unroll
    for (int i = 1; i < 12; i++) m = fmaxf(m, logit[i]);
    float w[12], s = 0.f;
#pragma unroll
    for (int i = 0; i < 12; i++) { w[i] = __expf(logit[i] - m); s += w[i]; }
    const float inv = 1.f / s;

    float o0 = 0.f, o1 = 0.f;
#pragma unroll
    for (int i = 0; i < 12; i++) {
        const __half2 vh = *(const __half2*)(Vh + base + (long)rows[i] * K1);
        const float2 vf = __half22float2(vh);
        o0 += w[i] * vf.x;
        o1 += w[i] * vf.y;
    }
    o0 *= inv; o1 *= inv;

    *(__half2*)(A1 + (long)n * K1 + base) = __floats2half2_rn(o0, o1);
}

// ---------------- launch: 2-stream batch pipeline ----------------
extern "C" void kernel_launch(void* const* d_in, const int* in_sizes, int n_in,
                              void* d_out, int out_size) {
    const float* query = (const float*)d_in[0];
    const float* y  = (const float*)d_in[3];
    const float* Wq = (const float*)d_in[4];
    const float* Wk = (const float*)d_in[5];
    const float* Wv = (const float*)d_in[6];
    const float* Wo = (const float*)d_in[7];
    const float* bo = (const float*)d_in[8];
    float* out = (float*)d_out;

    __half *xy1, *w1, *a1, *Kh, *Vh;
    float *Qf;
    cudaGetSymbolAddress((void**)&xy1, g_xy1);
    cudaGetSymbolAddress((void**)&w1,  g_w1);
    cudaGetSymbolAddress((void**)&a1,  g_a1);
    cudaGetSymbolAddress((void**)&Qf,  g_Qf);
    cudaGetSymbolAddress((void**)&Kh,  g_Kh);
    cudaGetSymbolAddress((void**)&Vh,  g_Vh);
    __half* wq1 = w1;
    __half* wk1 = w1 + (long)D_ * K1;
    __half* wv1 = w1 + 2L * D_ * K1;
    __half* wo1 = w1 + 3L * D_ * K1;

    const int smQKV = SM_HALVES * 2;    // 110592
    const int smO   = SMO_HALVES * 2;   // 82944
    cudaFuncSetAttribute(hgemm_qkv, cudaFuncAttributeMaxDynamicSharedMemorySize, smQKV);
    cudaFuncSetAttribute(hgemm_o,   cudaFuncAttributeMaxDynamicSharedMemorySize, smO);

    build_all_kernel<<<dim3(128, 8), 256>>>(query, y, Wq, Wk, Wv, Wo);

    cudaEventRecord(g_hx.eFork, 0);
    cudaStreamWaitEvent(g_hx.s1, g_hx.eFork, 0);

    for (int b = 0; b < B_; b++) {
        cudaStream_t st = (b == 0) ? (cudaStream_t)0 : g_hx.s1;
        __half* xyb = xy1 + (long)b * XYR * K1;
        float*  Qb  = Qf  + (long)b * N_  * D_;
        __half* Kb  = Kh  + (long)b * XYR * D_;
        __half* Vb  = Vh  + (long)b * XYR * D_;
        __half* ab  = a1  + (long)b * N_  * K1;
        float*  ob  = out + (long)b * N_  * D_;

        hgemm_qkv<<<640, 256, smQKV, st>>>(xyb, wq1, wk1, wv1, Qb, Kb, Vb);
        attn_kernel<<<N_, 512, 0, st>>>(Qb, Kb, Vb, ab);
        hgemm_o<<<256, 128, smO, st>>>(ab, wo1, ob, bo);
    }

    cudaEventRecord(g_hx.eJoin, g_hx.s1);
    cudaStreamWaitEvent((cudaStream_t)0, g_hx.eJoin, 0);
}